// round 7
// baseline (speedup 1.0000x reference)
#include <cuda_runtime.h>
#include <cuda_bf16.h>

#define SEQ   4096
#define DEMB  512
#define NH    8
#define DK    64

// Scratch (allocation-free rule: __device__ globals)
__device__ float g_Q[SEQ * DEMB];
__device__ float g_K[SEQ * DEMB];
__device__ float g_V[SEQ * DEMB];
__device__ float g_ctx[SEQ * DEMB];
__device__ float g_y[SEQ * DEMB];

// ---------------------------------------------------------------------------
// Tiled fp32 GEMM: C[M,N] = A[M,K] @ B[K,N] + bias (+ resid)
// M=4096, N=512, K=512. BM=BN=64, BK=16, 256 threads, 4x4 micro-tile.
// which: 0->g_Q, 1->g_K, 2->g_V, 3->g_y (A := g_ctx, add resid)
// ---------------------------------------------------------------------------
__global__ __launch_bounds__(256) void gemm_proj(
    const float* __restrict__ A, const float* __restrict__ B,
    const float* __restrict__ bias, const float* __restrict__ resid,
    int which)
{
    __shared__ float As[16][68];   // [k][m]
    __shared__ float Bs[16][68];   // [k][n]

    float* Cb = (which == 0) ? g_Q : (which == 1) ? g_K : (which == 2) ? g_V : g_y;
    const float* Ap = (which == 3) ? g_ctx : A;

    const int n0 = blockIdx.x * 64;
    const int m0 = blockIdx.y * 64;
    const int tid = threadIdx.x;
    const int tx = tid & 15, ty = tid >> 4;
    const int tx4 = tx * 4, ty4 = ty * 4;

    const int arow = tid >> 2;           // 0..63
    const int ak4  = (tid & 3) * 4;      // 0,4,8,12
    const int bk   = tid >> 4;           // 0..15
    const int bn4  = (tid & 15) * 4;     // 0..60

    float acc[4][4] = {};

    for (int kt = 0; kt < DEMB; kt += 16) {
        float4 av = *(const float4*)&Ap[(m0 + arow) * DEMB + kt + ak4];
        As[ak4 + 0][arow] = av.x;
        As[ak4 + 1][arow] = av.y;
        As[ak4 + 2][arow] = av.z;
        As[ak4 + 3][arow] = av.w;
        float4 bv = *(const float4*)&B[(kt + bk) * DEMB + n0 + bn4];
        *(float4*)&Bs[bk][bn4] = bv;
        __syncthreads();

        #pragma unroll
        for (int k = 0; k < 16; ++k) {
            float4 a4 = *(const float4*)&As[k][ty4];
            float4 b4 = *(const float4*)&Bs[k][tx4];
            float aa[4] = {a4.x, a4.y, a4.z, a4.w};
            float bb[4] = {b4.x, b4.y, b4.z, b4.w};
            #pragma unroll
            for (int r = 0; r < 4; ++r)
                #pragma unroll
                for (int c = 0; c < 4; ++c)
                    acc[r][c] += aa[r] * bb[c];
        }
        __syncthreads();
    }

    float4 bb4 = *(const float4*)&bias[n0 + tx4];
    float bb[4] = {bb4.x, bb4.y, bb4.z, bb4.w};
    #pragma unroll
    for (int r = 0; r < 4; ++r) {
        int row = m0 + ty4 + r;
        float4 cv;
        cv.x = acc[r][0] + bb[0];
        cv.y = acc[r][1] + bb[1];
        cv.z = acc[r][2] + bb[2];
        cv.w = acc[r][3] + bb[3];
        if (which == 3) {
            float4 rv = *(const float4*)&resid[row * DEMB + n0 + tx4];
            cv.x += rv.x; cv.y += rv.y; cv.z += rv.z; cv.w += rv.w;
        }
        *(float4*)&Cb[row * DEMB + n0 + tx4] = cv;
    }
}

// ---------------------------------------------------------------------------
// Flash attention, fp32. grid = (SEQ/64, NH). 256 threads.
// Tiles: 64 queries x 64 keys, online softmax, ctx accumulated in registers.
// Dynamic smem: Qt[d][i], Kt[d][j], Vs[j][d], Pt[j][i], pitch 68 floats.
// ---------------------------------------------------------------------------
#define FPITCH 68
#define FLASH_SMEM (4 * 64 * FPITCH * (int)sizeof(float))

__global__ __launch_bounds__(256) void flash_kernel()
{
    extern __shared__ float sm[];
    float* Qt = sm;                    // [64][68]  (d, i)
    float* Kt = sm + 64 * FPITCH;      // (d, j)
    float* Vs = sm + 2 * 64 * FPITCH;  // (j, d)
    float* Pt = sm + 3 * 64 * FPITCH;  // (j, i)

    const int tid = threadIdx.x;
    const int tx = tid & 15, ty = tid >> 4;
    const int tx4 = tx * 4, ty4 = ty * 4;
    const int q0 = blockIdx.x * 64;
    const int colbase = blockIdx.y * DK;

    // Load Q tile, transposed to (d, i)
    {
        const int i  = tid >> 4;
        const int d4 = (tid & 15) * 4;
        #pragma unroll
        for (int it = 0; it < 4; ++it) {
            int row = i + it * 16;
            float4 v = *(const float4*)&g_Q[(q0 + row) * DEMB + colbase + d4];
            Qt[(d4 + 0) * FPITCH + row] = v.x;
            Qt[(d4 + 1) * FPITCH + row] = v.y;
            Qt[(d4 + 2) * FPITCH + row] = v.z;
            Qt[(d4 + 3) * FPITCH + row] = v.w;
        }
    }

    float o[4][4] = {};
    float mrun[4] = {-1e30f, -1e30f, -1e30f, -1e30f};
    float lrun[4] = {};

    for (int kb = 0; kb < SEQ / 64; ++kb) {
        __syncthreads();   // previous iteration's Kt/Vs/Pt readers done
        {
            const int j  = tid >> 4;
            const int d4 = (tid & 15) * 4;
            #pragma unroll
            for (int it = 0; it < 4; ++it) {
                int row = j + it * 16;
                int gidx = (kb * 64 + row) * DEMB + colbase + d4;
                float4 kv = *(const float4*)&g_K[gidx];
                Kt[(d4 + 0) * FPITCH + row] = kv.x;
                Kt[(d4 + 1) * FPITCH + row] = kv.y;
                Kt[(d4 + 2) * FPITCH + row] = kv.z;
                Kt[(d4 + 3) * FPITCH + row] = kv.w;
                float4 vv = *(const float4*)&g_V[gidx];
                *(float4*)&Vs[row * FPITCH + d4] = vv;
            }
        }
        __syncthreads();

        // s = Q K^T  (4x4 per thread)
        float sc[4][4] = {};
        #pragma unroll 8
        for (int d = 0; d < DK; ++d) {
            float4 q4 = *(const float4*)&Qt[d * FPITCH + ty4];
            float4 k4 = *(const float4*)&Kt[d * FPITCH + tx4];
            float qa[4] = {q4.x, q4.y, q4.z, q4.w};
            float ka[4] = {k4.x, k4.y, k4.z, k4.w};
            #pragma unroll
            for (int r = 0; r < 4; ++r)
                #pragma unroll
                for (int c = 0; c < 4; ++c)
                    sc[r][c] += qa[r] * ka[c];
        }

        // online softmax (rows = ty4+r, reduce over tx with shfl width 16)
        #pragma unroll
        for (int r = 0; r < 4; ++r) {
            #pragma unroll
            for (int c = 0; c < 4; ++c) sc[r][c] *= 0.125f;  // 1/sqrt(64)
            float mb = fmaxf(fmaxf(sc[r][0], sc[r][1]), fmaxf(sc[r][2], sc[r][3]));
            mb = fmaxf(mb, __shfl_xor_sync(0xffffffffu, mb, 1));
            mb = fmaxf(mb, __shfl_xor_sync(0xffffffffu, mb, 2));
            mb = fmaxf(mb, __shfl_xor_sync(0xffffffffu, mb, 4));
            mb = fmaxf(mb, __shfl_xor_sync(0xffffffffu, mb, 8));
            float nm = fmaxf(mrun[r], mb);
            float alpha = __expf(mrun[r] - nm);
            float ls = 0.f;
            #pragma unroll
            for (int c = 0; c < 4; ++c) {
                float p = __expf(sc[r][c] - nm);
                Pt[(tx4 + c) * FPITCH + ty4 + r] = p;   // (j, i)
                ls += p;
            }
            ls += __shfl_xor_sync(0xffffffffu, ls, 1);
            ls += __shfl_xor_sync(0xffffffffu, ls, 2);
            ls += __shfl_xor_sync(0xffffffffu, ls, 4);
            ls += __shfl_xor_sync(0xffffffffu, ls, 8);
            lrun[r] = lrun[r] * alpha + ls;
            mrun[r] = nm;
            #pragma unroll
            for (int c = 0; c < 4; ++c) o[r][c] *= alpha;
        }
        __syncthreads();

        // o += P @ V
        #pragma unroll 8
        for (int j = 0; j < 64; ++j) {
            float4 p4 = *(const float4*)&Pt[j * FPITCH + ty4];
            float4 v4 = *(const float4*)&Vs[j * FPITCH + tx4];
            float pa[4] = {p4.x, p4.y, p4.z, p4.w};
            float va[4] = {v4.x, v4.y, v4.z, v4.w};
            #pragma unroll
            for (int r = 0; r < 4; ++r)
                #pragma unroll
                for (int c = 0; c < 4; ++c)
                    o[r][c] += pa[r] * va[c];
        }
    }

    #pragma unroll
    for (int r = 0; r < 4; ++r) {
        float inv = 1.0f / lrun[r];
        float4 ov = make_float4(o[r][0] * inv, o[r][1] * inv,
                                o[r][2] * inv, o[r][3] * inv);
        *(float4*)&g_ctx[(q0 + ty4 + r) * DEMB + colbase + tx4] = ov;
    }
}

// ---------------------------------------------------------------------------
// LayerNorm over rows of g_y -> out. 128 threads/row, float4 per thread.
// ---------------------------------------------------------------------------
__global__ __launch_bounds__(128) void ln_kernel(
    const float* __restrict__ gamma, const float* __restrict__ beta,
    float* __restrict__ out)
{
    const int row = blockIdx.x;
    const int tid = threadIdx.x;
    float4 v = *(const float4*)&g_y[row * DEMB + tid * 4];
    float s = v.x + v.y + v.z + v.w;
    float q = v.x * v.x + v.y * v.y + v.z * v.z + v.w * v.w;
    #pragma unroll
    for (int m = 16; m; m >>= 1) {
        s += __shfl_xor_sync(0xffffffffu, s, m);
        q += __shfl_xor_sync(0xffffffffu, q, m);
    }
    __shared__ float ss[4], qq[4];
    if ((tid & 31) == 0) { ss[tid >> 5] = s; qq[tid >> 5] = q; }
    __syncthreads();
    s = ss[0] + ss[1] + ss[2] + ss[3];
    q = qq[0] + qq[1] + qq[2] + qq[3];
    const float mean = s * (1.0f / DEMB);
    const float var  = q * (1.0f / DEMB) - mean * mean;
    const float rstd = rsqrtf(var + 1e-5f);
    float4 g = *(const float4*)&gamma[tid * 4];
    float4 b = *(const float4*)&beta[tid * 4];
    float4 ov;
    ov.x = (v.x - mean) * rstd * g.x + b.x;
    ov.y = (v.y - mean) * rstd * g.y + b.y;
    ov.z = (v.z - mean) * rstd * g.z + b.z;
    ov.w = (v.w - mean) * rstd * g.w + b.w;
    *(float4*)&out[row * DEMB + tid * 4] = ov;
}

// ---------------------------------------------------------------------------
extern "C" void kernel_launch(void* const* d_in, const int* in_sizes, int n_in,
                              void* d_out, int out_size)
{
    const float* x     = (const float*)d_in[0];
    const float* Wq    = (const float*)d_in[1];
    const float* bq    = (const float*)d_in[2];
    const float* Wk    = (const float*)d_in[3];
    const float* bk    = (const float*)d_in[4];
    const float* Wv    = (const float*)d_in[5];
    const float* bv    = (const float*)d_in[6];
    const float* Wo    = (const float*)d_in[7];
    const float* bo    = (const float*)d_in[8];
    const float* gamma = (const float*)d_in[9];
    const float* beta  = (const float*)d_in[10];
    float* out = (float*)d_out;

    dim3 ggrid(DEMB / 64, SEQ / 64);   // (8, 64)
    gemm_proj<<<ggrid, 256>>>(x, Wq, bq, nullptr, 0);
    gemm_proj<<<ggrid, 256>>>(x, Wk, bk, nullptr, 1);
    gemm_proj<<<ggrid, 256>>>(x, Wv, bv, nullptr, 2);

    cudaFuncSetAttribute(flash_kernel,
                         cudaFuncAttributeMaxDynamicSharedMemorySize, FLASH_SMEM);
    flash_kernel<<<dim3(SEQ / 64, NH), 256, FLASH_SMEM>>>();

    gemm_proj<<<ggrid, 256>>>(x, Wo, bo, x, 3);   // A := g_ctx internally, +x resid
    ln_kernel<<<SEQ, 128>>>(gamma, beta, out);
}

// round 8
// speedup vs baseline: 2.3365x; 2.3365x over previous
#include <cuda_runtime.h>
#include <cuda_bf16.h>
#include <cstdint>

#define SEQ   4096
#define DEMB  512
#define NH    8
#define DK    64

// Scratch (allocation-free rule: __device__ globals)
__device__ float g_Q[SEQ * DEMB];
__device__ float g_K[SEQ * DEMB];
__device__ float g_V[SEQ * DEMB];
__device__ float g_ctx[SEQ * DEMB];
__device__ float g_y[SEQ * DEMB];

// ---------------------------------------------------------------------------
// tf32 helpers
// ---------------------------------------------------------------------------
__device__ __forceinline__ uint32_t f2tf(float f) {
    uint32_t u;
    asm("cvt.rna.tf32.f32 %0, %1;" : "=r"(u) : "f"(f));
    return u;
}

__device__ __forceinline__ void mma_tf32(float c[4], const uint32_t a[4],
                                         uint32_t b0, uint32_t b1) {
    asm("mma.sync.aligned.m16n8k8.row.col.f32.tf32.tf32.f32 "
        "{%0,%1,%2,%3}, {%4,%5,%6,%7}, {%8,%9}, {%0,%1,%2,%3};"
        : "+f"(c[0]), "+f"(c[1]), "+f"(c[2]), "+f"(c[3])
        : "r"(a[0]), "r"(a[1]), "r"(a[2]), "r"(a[3]), "r"(b0), "r"(b1));
}

// ---------------------------------------------------------------------------
// Tiled fp32 GEMM: C[M,N] = A[M,K] @ B[K,N] + bias (+ resid)  [unchanged]
// ---------------------------------------------------------------------------
__global__ __launch_bounds__(256) void gemm_proj(
    const float* __restrict__ A, const float* __restrict__ B,
    const float* __restrict__ bias, const float* __restrict__ resid,
    int which)
{
    __shared__ float As[16][68];   // [k][m]
    __shared__ float Bs[16][68];   // [k][n]

    float* Cb = (which == 0) ? g_Q : (which == 1) ? g_K : (which == 2) ? g_V : g_y;
    const float* Ap = (which == 3) ? g_ctx : A;

    const int n0 = blockIdx.x * 64;
    const int m0 = blockIdx.y * 64;
    const int tid = threadIdx.x;
    const int tx = tid & 15, ty = tid >> 4;
    const int tx4 = tx * 4, ty4 = ty * 4;

    const int arow = tid >> 2;
    const int ak4  = (tid & 3) * 4;
    const int bk   = tid >> 4;
    const int bn4  = (tid & 15) * 4;

    float acc[4][4] = {};

    for (int kt = 0; kt < DEMB; kt += 16) {
        float4 av = *(const float4*)&Ap[(m0 + arow) * DEMB + kt + ak4];
        As[ak4 + 0][arow] = av.x;
        As[ak4 + 1][arow] = av.y;
        As[ak4 + 2][arow] = av.z;
        As[ak4 + 3][arow] = av.w;
        float4 bv = *(const float4*)&B[(kt + bk) * DEMB + n0 + bn4];
        *(float4*)&Bs[bk][bn4] = bv;
        __syncthreads();

        #pragma unroll
        for (int k = 0; k < 16; ++k) {
            float4 a4 = *(const float4*)&As[k][ty4];
            float4 b4 = *(const float4*)&Bs[k][tx4];
            float aa[4] = {a4.x, a4.y, a4.z, a4.w};
            float bb[4] = {b4.x, b4.y, b4.z, b4.w};
            #pragma unroll
            for (int r = 0; r < 4; ++r)
                #pragma unroll
                for (int c = 0; c < 4; ++c)
                    acc[r][c] += aa[r] * bb[c];
        }
        __syncthreads();
    }

    float4 bb4 = *(const float4*)&bias[n0 + tx4];
    float bb[4] = {bb4.x, bb4.y, bb4.z, bb4.w};
    #pragma unroll
    for (int r = 0; r < 4; ++r) {
        int row = m0 + ty4 + r;
        float4 cv;
        cv.x = acc[r][0] + bb[0];
        cv.y = acc[r][1] + bb[1];
        cv.z = acc[r][2] + bb[2];
        cv.w = acc[r][3] + bb[3];
        if (which == 3) {
            float4 rv = *(const float4*)&resid[row * DEMB + n0 + tx4];
            cv.x += rv.x; cv.y += rv.y; cv.z += rv.z; cv.w += rv.w;
        }
        *(float4*)&Cb[row * DEMB + n0 + tx4] = cv;
    }
}

// ---------------------------------------------------------------------------
// Flash attention, tf32 mma.sync (m16n8k8), fp32 accumulation.
// 256 threads = 8 warps. Q-tile = 128 rows (16 rows/warp, A-frags in regs),
// K-tile = 64 keys. grid = (SEQ/128, NH).
// smem: Ks[64][68], Vs[64][72], Ps[128][68]  (all tf32-rounded fp32 bits)
// ---------------------------------------------------------------------------
#define KS_PITCH 68
#define VS_PITCH 72
#define PS_PITCH 68
#define KS_OFF 0
#define VS_OFF (64 * KS_PITCH)
#define PS_OFF (VS_OFF + 64 * VS_PITCH)
#define FLASH_SMEM_F (PS_OFF + 128 * PS_PITCH)
#define FLASH_SMEM_B (FLASH_SMEM_F * (int)sizeof(float))

__global__ __launch_bounds__(256, 2) void flash_tf32()
{
    extern __shared__ float sm[];
    float* Ks = sm + KS_OFF;
    float* Vs = sm + VS_OFF;
    float* Ps = sm + PS_OFF;

    const int tid  = threadIdx.x;
    const int w    = tid >> 5;
    const int lane = tid & 31;
    const int g    = lane >> 2;   // group id: row within fragment
    const int q    = lane & 3;    // quad position
    const int q0   = blockIdx.x * 128;
    const int cb   = blockIdx.y * DK;

    const int r0 = q0 + w * 16 + g;   // first query row of this thread
    const int r1 = r0 + 8;

    // Q A-fragments (loop-invariant): qf[c] covers d = c*8 .. c*8+7
    uint32_t qf[8][4];
    #pragma unroll
    for (int c = 0; c < 8; ++c) {
        qf[c][0] = f2tf(g_Q[r0 * DEMB + cb + c * 8 + q]);
        qf[c][1] = f2tf(g_Q[r1 * DEMB + cb + c * 8 + q]);
        qf[c][2] = f2tf(g_Q[r0 * DEMB + cb + c * 8 + q + 4]);
        qf[c][3] = f2tf(g_Q[r1 * DEMB + cb + c * 8 + q + 4]);
    }

    float o[8][4];
    #pragma unroll
    for (int n = 0; n < 8; ++n)
        #pragma unroll
        for (int i = 0; i < 4; ++i) o[n][i] = 0.f;
    float m0 = -1e30f, m1 = -1e30f, l0 = 0.f, l1 = 0.f;

    const int lrow = tid >> 2;        // 0..63 : K/V tile row this thread loads
    const int lc16 = (tid & 3) * 16;  // 16-float column chunk

    const int prow0 = w * 16 + g;     // local P row (first)
    const int prow1 = prow0 + 8;

    for (int kb = 0; kb < SEQ / 64; ++kb) {
        __syncthreads();   // all warps done reading Ks/Vs of previous tile
        {
            int grow = kb * 64 + lrow;
            const float4* kp = (const float4*)&g_K[grow * DEMB + cb + lc16];
            const float4* vp = (const float4*)&g_V[grow * DEMB + cb + lc16];
            #pragma unroll
            for (int i = 0; i < 4; ++i) {
                float4 kv = kp[i];
                Ks[lrow * KS_PITCH + lc16 + i * 4 + 0] = __uint_as_float(f2tf(kv.x));
                Ks[lrow * KS_PITCH + lc16 + i * 4 + 1] = __uint_as_float(f2tf(kv.y));
                Ks[lrow * KS_PITCH + lc16 + i * 4 + 2] = __uint_as_float(f2tf(kv.z));
                Ks[lrow * KS_PITCH + lc16 + i * 4 + 3] = __uint_as_float(f2tf(kv.w));
                float4 vv = vp[i];
                Vs[lrow * VS_PITCH + lc16 + i * 4 + 0] = __uint_as_float(f2tf(vv.x));
                Vs[lrow * VS_PITCH + lc16 + i * 4 + 1] = __uint_as_float(f2tf(vv.y));
                Vs[lrow * VS_PITCH + lc16 + i * 4 + 2] = __uint_as_float(f2tf(vv.z));
                Vs[lrow * VS_PITCH + lc16 + i * 4 + 3] = __uint_as_float(f2tf(vv.w));
            }
        }
        __syncthreads();

        // ---- S = Q K^T : sc[n] covers keys n*8..n*8+7 ----
        float sc[8][4];
        #pragma unroll
        for (int n = 0; n < 8; ++n)
            #pragma unroll
            for (int i = 0; i < 4; ++i) sc[n][i] = 0.f;

        #pragma unroll
        for (int c = 0; c < 8; ++c) {
            #pragma unroll
            for (int n = 0; n < 8; ++n) {
                // B[k=d][n=key], col-major: b0 at d=c*8+q, key=n*8+g
                uint32_t b0 = __float_as_uint(Ks[(n * 8 + g) * KS_PITCH + c * 8 + q]);
                uint32_t b1 = __float_as_uint(Ks[(n * 8 + g) * KS_PITCH + c * 8 + q + 4]);
                mma_tf32(sc[n], qf[c], b0, b1);
            }
        }

        // ---- scale + online softmax ----
        float tmax0 = -1e30f, tmax1 = -1e30f;
        #pragma unroll
        for (int n = 0; n < 8; ++n) {
            sc[n][0] *= 0.125f; sc[n][1] *= 0.125f;
            sc[n][2] *= 0.125f; sc[n][3] *= 0.125f;
            tmax0 = fmaxf(tmax0, fmaxf(sc[n][0], sc[n][1]));
            tmax1 = fmaxf(tmax1, fmaxf(sc[n][2], sc[n][3]));
        }
        tmax0 = fmaxf(tmax0, __shfl_xor_sync(0xffffffffu, tmax0, 1));
        tmax0 = fmaxf(tmax0, __shfl_xor_sync(0xffffffffu, tmax0, 2));
        tmax1 = fmaxf(tmax1, __shfl_xor_sync(0xffffffffu, tmax1, 1));
        tmax1 = fmaxf(tmax1, __shfl_xor_sync(0xffffffffu, tmax1, 2));

        float nm0 = fmaxf(m0, tmax0), nm1 = fmaxf(m1, tmax1);
        float al0 = __expf(m0 - nm0), al1 = __expf(m1 - nm1);
        float s0 = 0.f, s1 = 0.f;
        #pragma unroll
        for (int n = 0; n < 8; ++n) {
            float p00 = __expf(sc[n][0] - nm0);
            float p01 = __expf(sc[n][1] - nm0);
            float p10 = __expf(sc[n][2] - nm1);
            float p11 = __expf(sc[n][3] - nm1);
            s0 += p00 + p01;
            s1 += p10 + p11;
            Ps[prow0 * PS_PITCH + n * 8 + 2 * q]     = __uint_as_float(f2tf(p00));
            Ps[prow0 * PS_PITCH + n * 8 + 2 * q + 1] = __uint_as_float(f2tf(p01));
            Ps[prow1 * PS_PITCH + n * 8 + 2 * q]     = __uint_as_float(f2tf(p10));
            Ps[prow1 * PS_PITCH + n * 8 + 2 * q + 1] = __uint_as_float(f2tf(p11));
        }
        s0 += __shfl_xor_sync(0xffffffffu, s0, 1);
        s0 += __shfl_xor_sync(0xffffffffu, s0, 2);
        s1 += __shfl_xor_sync(0xffffffffu, s1, 1);
        s1 += __shfl_xor_sync(0xffffffffu, s1, 2);
        l0 = l0 * al0 + s0;
        l1 = l1 * al1 + s1;
        m0 = nm0; m1 = nm1;
        #pragma unroll
        for (int n = 0; n < 8; ++n) {
            o[n][0] *= al0; o[n][1] *= al0;
            o[n][2] *= al1; o[n][3] *= al1;
        }
        __syncwarp();   // Ps rows are private to this warp; make writes visible

        // ---- O += P V : o[n] covers d = n*8..n*8+7 ----
        #pragma unroll
        for (int c = 0; c < 8; ++c) {          // key chunk c*8..c*8+7
            uint32_t a[4];
            a[0] = __float_as_uint(Ps[prow0 * PS_PITCH + c * 8 + q]);
            a[1] = __float_as_uint(Ps[prow1 * PS_PITCH + c * 8 + q]);
            a[2] = __float_as_uint(Ps[prow0 * PS_PITCH + c * 8 + q + 4]);
            a[3] = __float_as_uint(Ps[prow1 * PS_PITCH + c * 8 + q + 4]);
            #pragma unroll
            for (int n = 0; n < 8; ++n) {
                // B[k=key][n=d], col-major: b0 at key=c*8+q, d=n*8+g
                uint32_t b0 = __float_as_uint(Vs[(c * 8 + q) * VS_PITCH + n * 8 + g]);
                uint32_t b1 = __float_as_uint(Vs[(c * 8 + q + 4) * VS_PITCH + n * 8 + g]);
                mma_tf32(o[n], a, b0, b1);
            }
        }
    }

    float inv0 = 1.f / l0, inv1 = 1.f / l1;
    #pragma unroll
    for (int n = 0; n < 8; ++n) {
        g_ctx[r0 * DEMB + cb + n * 8 + 2 * q]     = o[n][0] * inv0;
        g_ctx[r0 * DEMB + cb + n * 8 + 2 * q + 1] = o[n][1] * inv0;
        g_ctx[r1 * DEMB + cb + n * 8 + 2 * q]     = o[n][2] * inv1;
        g_ctx[r1 * DEMB + cb + n * 8 + 2 * q + 1] = o[n][3] * inv1;
    }
}

// ---------------------------------------------------------------------------
// LayerNorm over rows of g_y -> out. [unchanged]
// ---------------------------------------------------------------------------
__global__ __launch_bounds__(128) void ln_kernel(
    const float* __restrict__ gamma, const float* __restrict__ beta,
    float* __restrict__ out)
{
    const int row = blockIdx.x;
    const int tid = threadIdx.x;
    float4 v = *(const float4*)&g_y[row * DEMB + tid * 4];
    float s = v.x + v.y + v.z + v.w;
    float q = v.x * v.x + v.y * v.y + v.z * v.z + v.w * v.w;
    #pragma unroll
    for (int m = 16; m; m >>= 1) {
        s += __shfl_xor_sync(0xffffffffu, s, m);
        q += __shfl_xor_sync(0xffffffffu, q, m);
    }
    __shared__ float ss[4], qq[4];
    if ((tid & 31) == 0) { ss[tid >> 5] = s; qq[tid >> 5] = q; }
    __syncthreads();
    s = ss[0] + ss[1] + ss[2] + ss[3];
    q = qq[0] + qq[1] + qq[2] + qq[3];
    const float mean = s * (1.0f / DEMB);
    const float var  = q * (1.0f / DEMB) - mean * mean;
    const float rstd = rsqrtf(var + 1e-5f);
    float4 g = *(const float4*)&gamma[tid * 4];
    float4 b = *(const float4*)&beta[tid * 4];
    float4 ov;
    ov.x = (v.x - mean) * rstd * g.x + b.x;
    ov.y = (v.y - mean) * rstd * g.y + b.y;
    ov.z = (v.z - mean) * rstd * g.z + b.z;
    ov.w = (v.w - mean) * rstd * g.w + b.w;
    *(float4*)&out[row * DEMB + tid * 4] = ov;
}

// ---------------------------------------------------------------------------
extern "C" void kernel_launch(void* const* d_in, const int* in_sizes, int n_in,
                              void* d_out, int out_size)
{
    const float* x     = (const float*)d_in[0];
    const float* Wq    = (const float*)d_in[1];
    const float* bq    = (const float*)d_in[2];
    const float* Wk    = (const float*)d_in[3];
    const float* bk    = (const float*)d_in[4];
    const float* Wv    = (const float*)d_in[5];
    const float* bv    = (const float*)d_in[6];
    const float* Wo    = (const float*)d_in[7];
    const float* bo    = (const float*)d_in[8];
    const float* gamma = (const float*)d_in[9];
    const float* beta  = (const float*)d_in[10];
    float* out = (float*)d_out;

    dim3 ggrid(DEMB / 64, SEQ / 64);   // (8, 64)
    gemm_proj<<<ggrid, 256>>>(x, Wq, bq, nullptr, 0);
    gemm_proj<<<ggrid, 256>>>(x, Wk, bk, nullptr, 1);
    gemm_proj<<<ggrid, 256>>>(x, Wv, bv, nullptr, 2);

    cudaFuncSetAttribute(flash_tf32,
                         cudaFuncAttributeMaxDynamicSharedMemorySize, FLASH_SMEM_B);
    flash_tf32<<<dim3(SEQ / 128, NH), 256, FLASH_SMEM_B>>>();

    gemm_proj<<<ggrid, 256>>>(x, Wo, bo, x, 3);   // A := g_ctx internally, +x resid
    ln_kernel<<<SEQ, 128>>>(gamma, beta, out);
}